// round 8
// baseline (speedup 1.0000x reference)
#include <cuda_runtime.h>
#include <math.h>
#include <stdint.h>

#define NB    8192      // batch
#define DK    768       // key dim
#define DIM   768       // embedding dim
#define POOL  30
#define PLEN  20
#define TOPK  5
#define HALF  10        // PLEN/2

// Scratch (no allocation allowed).
__device__ float g_nk[POOL * DK];
__device__ int   g_idx[NB * TOPK];

// ---------------------------------------------------------------------------
// Kernel 0: normalize K rows. 30 blocks x 32 threads (validated round 6).
// ---------------------------------------------------------------------------
__global__ __launch_bounds__(32) void norm_kernel(const float* __restrict__ K) {
    int w    = blockIdx.x;
    int lane = threadIdx.x;

    const float4* k4 = reinterpret_cast<const float4*>(K) + w * (DK / 4);
    float4 v[6];
    float ss = 0.0f;
#pragma unroll
    for (int j = 0; j < 6; j++) {
        v[j] = __ldg(k4 + j * 32 + lane);
        ss += v[j].x * v[j].x + v[j].y * v[j].y + v[j].z * v[j].z + v[j].w * v[j].w;
    }
#pragma unroll
    for (int off = 16; off; off >>= 1)
        ss += __shfl_xor_sync(0xFFFFFFFFu, ss, off);

    float inv = 1.0f / sqrtf(fmaxf(ss, 1e-24f));   // matches max(norm,1e-12)
    float4* o = reinterpret_cast<float4*>(g_nk) + w * (DK / 4);
#pragma unroll
    for (int j = 0; j < 6; j++) {
        float4 r = v[j];
        r.x *= inv; r.y *= inv; r.z *= inv; r.w *= inv;
        o[j * 32 + lane] = r;
    }
}

// ---------------------------------------------------------------------------
// Kernel 1: cosine-sim top-5 (validated round 6, + row offset).
// Block = 4 warps = 16 rows, one warp -> 4 rows, butterfly truncated at 3.
// ---------------------------------------------------------------------------
__global__ __launch_bounds__(128) void topk_kernel(const float* __restrict__ xq,
                                                   int rowOff) {
    int lane = threadIdx.x & 31;
    int wInB = threadIdx.x >> 5;
    int row0 = rowOff + blockIdx.x * 16;
    int rBase = wInB * 4;

    __shared__ float s_part[16][POOL][4];

    const float4* q4 = reinterpret_cast<const float4*>(xq);
    float4 q[4][6];
#pragma unroll
    for (int r = 0; r < 4; r++) {
        const float4* src = q4 + (size_t)(row0 + rBase + r) * (DK / 4);
#pragma unroll
        for (int j = 0; j < 6; j++)
            q[r][j] = __ldg(src + j * 32 + lane);
    }

    const float4* nk4 = reinterpret_cast<const float4*>(g_nk);
    for (int k = 0; k < POOL; k++) {
        float a0 = 0.f, a1 = 0.f, a2 = 0.f, a3 = 0.f;
        const float4* nk = nk4 + k * (DK / 4);
#pragma unroll
        for (int j = 0; j < 6; j++) {
            float4 n = __ldg(nk + j * 32 + lane);
            a0 += q[0][j].x * n.x + q[0][j].y * n.y + q[0][j].z * n.z + q[0][j].w * n.w;
            a1 += q[1][j].x * n.x + q[1][j].y * n.y + q[1][j].z * n.z + q[1][j].w * n.w;
            a2 += q[2][j].x * n.x + q[2][j].y * n.y + q[2][j].z * n.z + q[2][j].w * n.w;
            a3 += q[3][j].x * n.x + q[3][j].y * n.y + q[3][j].z * n.z + q[3][j].w * n.w;
        }
#pragma unroll
        for (int off = 16; off >= 4; off >>= 1) {
            a0 += __shfl_xor_sync(0xFFFFFFFFu, a0, off);
            a1 += __shfl_xor_sync(0xFFFFFFFFu, a1, off);
            a2 += __shfl_xor_sync(0xFFFFFFFFu, a2, off);
            a3 += __shfl_xor_sync(0xFFFFFFFFu, a3, off);
        }
        if (lane < 4) {
            s_part[rBase + 0][k][lane] = a0;
            s_part[rBase + 1][k][lane] = a1;
            s_part[rBase + 2][k][lane] = a2;
            s_part[rBase + 3][k][lane] = a3;
        }
    }
    __syncthreads();

    if (threadIdx.x < 16) {
        int lr  = threadIdx.x;
        int row = row0 + lr;
        float sims[POOL];
#pragma unroll
        for (int k = 0; k < POOL; k++)
            sims[k] = (s_part[lr][k][0] + s_part[lr][k][1])
                    + (s_part[lr][k][2] + s_part[lr][k][3]);
        unsigned used = 0;
#pragma unroll
        for (int t = 0; t < TOPK; t++) {
            float best = -3.4e38f;
            int   bi   = 0;
#pragma unroll
            for (int k = 0; k < POOL; k++) {
                if ((used >> k) & 1u) continue;
                float v = sims[k];
                if (v > best) { best = v; bi = k; }   // strict > => smallest idx ties
            }
            used |= (1u << bi);
            g_idx[row * TOPK + t] = bi;
        }
    }
}

// ---------------------------------------------------------------------------
// Kernel 2: gather — validated round-1 body (92.7% DRAM), + row offset.
// ---------------------------------------------------------------------------
__global__ __launch_bounds__(256) void gather_kernel(const float* __restrict__ p,
                                                     float* __restrict__ out,
                                                     int rowOff) {
    int t = blockIdx.x;            // 0..4
    int b = rowOff + blockIdx.y;   // batch row
    int k = g_idx[b * TOPK + t];

    const float4* src  = reinterpret_cast<const float4*>(p) + (size_t)k * (PLEN * DIM / 4);
    float4*       out4 = reinterpret_cast<float4*>(out);

    const size_t base0 = ((size_t)b * (TOPK * HALF) + (size_t)t * HALF) * (DIM / 4);
    const size_t base1 = ((size_t)(NB + b) * (TOPK * HALF) + (size_t)t * HALF) * (DIM / 4);
    const int    halfN = HALF * DIM / 4;   // 1920 float4 per half

#pragma unroll 5
    for (int i = threadIdx.x; i < PLEN * DIM / 4; i += 256) {
        float4 v = __ldg(src + i);
        if (i < halfN) out4[base0 + i] = v;
        else           out4[base1 + (i - halfN)] = v;
    }
}

// ---------------------------------------------------------------------------
// Pipelined launch: topk chunk c+1 (side stream) overlaps gather chunk c
// (main stream). Streams/events created once on first call (infra only —
// enqueued GPU work is identical every call).
// ---------------------------------------------------------------------------
#define NCHUNK 4
static const int c_off[NCHUNK + 1] = {0, 512, 2048, 4096, 8192};

extern "C" void kernel_launch(void* const* d_in, const int* in_sizes, int n_in,
                              void* d_out, int out_size) {
    const float* xq = (const float*)d_in[0];   // x_query [8192,768]
    // d_in[1] = x (unused)
    const float* K  = (const float*)d_in[2];   // [30,768]
    const float* p  = (const float*)d_in[3];   // [30,20,768]
    float*       out = (float*)d_out;          // [2,8192,50,768]

    static cudaStream_t s2 = nullptr;
    static cudaEvent_t  evFork = nullptr;
    static cudaEvent_t  evT[NCHUNK] = {nullptr, nullptr, nullptr, nullptr};
    if (s2 == nullptr) {
        cudaStreamCreateWithFlags(&s2, cudaStreamNonBlocking);
        cudaEventCreateWithFlags(&evFork, cudaEventDisableTiming);
        for (int c = 0; c < NCHUNK; c++)
            cudaEventCreateWithFlags(&evT[c], cudaEventDisableTiming);
    }

    // Fork side stream off the (captured) default stream.
    cudaEventRecord(evFork, 0);
    cudaStreamWaitEvent(s2, evFork, 0);

    // Side stream: norm, then topk chunks back-to-back, event after each.
    norm_kernel<<<POOL, 32, 0, s2>>>(K);
    for (int c = 0; c < NCHUNK; c++) {
        int rows = c_off[c + 1] - c_off[c];
        topk_kernel<<<rows / 16, 128, 0, s2>>>(xq, c_off[c]);
        cudaEventRecord(evT[c], s2);
    }

    // Main stream: gather chunk c as soon as its topk is done.
    for (int c = 0; c < NCHUNK; c++) {
        int rows = c_off[c + 1] - c_off[c];
        cudaStreamWaitEvent(0, evT[c], 0);
        gather_kernel<<<dim3(TOPK, rows), 256>>>(p, out, c_off[c]);
    }
}